// round 17
// baseline (speedup 1.0000x reference)
#include <cuda_runtime.h>
#include <stdint.h>

// keep[b][n] = 1 if node n is in the top-k of batch b. B=16, N=2048.
__device__ unsigned char g_keep[16 * 2048];

// ---------------------------------------------------------------------------
// Kernel 1: exact top-k via 8-bit radix select (converged, ~3us).
// Warp-shfl bin suffix-scan. Bit-exact jax.lax.top_k selection
// (value desc, ties -> lower index). One block per batch, 256 threads.
// Ends with PDL trigger.
// ---------------------------------------------------------------------------
__global__ void __launch_bounds__(256)
topk_radix_kernel(const float* __restrict__ score, int N, int k) {
    __shared__ unsigned u[2048];
    __shared__ unsigned hist[256];
    __shared__ unsigned s_prefix, s_kk;

    const int b   = blockIdx.x;
    const int tid = threadIdx.x;
    const float* sc = score + (size_t)b * N;

    for (int t = tid; t < N; t += 256) {
        unsigned x = __float_as_uint(sc[t]);
        x ^= (x & 0x80000000u) ? 0xFFFFFFFFu : 0x80000000u;  // order-preserving
        u[t] = x;
    }
    if (tid == 0) { s_prefix = 0u; s_kk = (unsigned)k; }
    __syncthreads();

    for (int shift = 24; shift >= 0; shift -= 8) {
        const unsigned prefix = s_prefix;
        const unsigned kk     = s_kk;
        const unsigned pmask  = (shift == 24) ? 0u : (0xFFFFFFFFu << (shift + 8));

        hist[tid] = 0u;
        __syncthreads();

        for (int t = tid; t < N; t += 256) {
            unsigned x = u[t];
            if ((x & pmask) == prefix)
                atomicAdd(&hist[(x >> shift) & 0xFFu], 1u);
        }
        __syncthreads();

        if (tid < 32) {
            unsigned v[8], p[8];
            unsigned acc = 0u;
#pragma unroll
            for (int i = 0; i < 8; i++) {
                v[i] = hist[255 - (tid * 8 + i)];
                acc += v[i];
                p[i] = acc;
            }
            unsigned lane_excl = 0u, run = acc;
#pragma unroll
            for (int off = 1; off < 32; off <<= 1) {
                unsigned n0 = __shfl_up_sync(0xFFFFFFFFu, run, off);
                if ((int)(tid) >= off) { lane_excl += n0; run += n0; }
            }
#pragma unroll
            for (int i = 0; i < 8; i++) {
                unsigned incl = lane_excl + p[i];
                unsigned excl = incl - v[i];
                if (excl < kk && incl >= kk) {
                    int bin = 255 - (tid * 8 + i);
                    s_prefix = prefix | ((unsigned)bin << shift);
                    s_kk     = kk - excl;
                }
            }
        }
        __syncthreads();
    }

    const unsigned T        = s_prefix;
    const unsigned need_eq  = s_kk;
    const unsigned total_eq = hist[T & 0xFFu];

    for (int t = tid; t < N; t += 256) {
        unsigned x = u[t];
        unsigned char kp = 0u;
        if (x > T) {
            kp = 1u;
        } else if (x == T) {
            if (total_eq == need_eq) {
                kp = 1u;
            } else {
                unsigned c = 0u;
                for (int j = 0; j < t; j++) c += (u[j] == T);
                kp = (c < need_eq) ? 1u : 0u;
            }
        }
        g_keep[b * N + t] = kp;
    }

    __threadfence();
    __syncthreads();
    if (tid == 0) cudaTriggerProgrammaticLaunchCompletion();
}

// ---- sm_103a 256-bit global ld/st (PTX ISA 8.7+, v8.b32) ----
#define LDG256(v, ptr)                                                        \
    asm volatile("ld.global.v8.b32 {%0,%1,%2,%3,%4,%5,%6,%7}, [%8];"          \
        : "=r"((v)[0]), "=r"((v)[1]), "=r"((v)[2]), "=r"((v)[3]),             \
          "=r"((v)[4]), "=r"((v)[5]), "=r"((v)[6]), "=r"((v)[7])              \
        : "l"(ptr))

#define STG256(ptr, v)                                                        \
    asm volatile("st.global.v8.b32 [%0], {%1,%2,%3,%4,%5,%6,%7,%8};"          \
        :: "l"(ptr),                                                          \
           "r"((v)[0]), "r"((v)[1]), "r"((v)[2]), "r"((v)[3]),                \
           "r"((v)[4]), "r"((v)[5]), "r"((v)[6]), "r"((v)[7])                 \
        : "memory");

// ---------------------------------------------------------------------------
// Kernel 2: out[b,i,j] = adj[b,i,j] * (keep[b,i] || keep[b,j])
// PDL secondary using 256-bit accesses: 2 rows per block, 256 threads,
// each thread prefetches two 32B chunks (64B in flight, half the LDG count
// of the float4 version) BEFORE cudaGridDependencySynchronize().
// Column mask: 8 keep-bytes per chunk read as one uint64; zeroing done on
// uint bit patterns (0x00000000 == 0.0f).
// Specialized for N==2048 w/ 256 threads; float4 fallback for other shapes.
// ---------------------------------------------------------------------------
__global__ void __launch_bounds__(256)
apply_mask_kernel(const float* __restrict__ adj,
                  float* __restrict__ out, int N) {
    const int tid = threadIdx.x;
    const int pairPerBatch = N >> 1;
    int r  = blockIdx.x;                       // row-pair index
    int b  = r / pairPerBatch;
    int i0 = (r - b * pairPerBatch) * 2;
    int i1 = i0 + 1;

    size_t e0 = ((size_t)b * N + i0) * N;      // element offset of row i0
    size_t e1 = e0 + N;

    if (N == 2048 && blockDim.x == 256) {
        const int c = tid * 8;                 // 8 floats = 32B per thread/row

        unsigned v0[8], v1[8];
        LDG256(v0, adj + e0 + c);
        LDG256(v1, adj + e1 + c);

        cudaGridDependencySynchronize();       // wait for g_keep

        const unsigned char* kb = g_keep + b * N;
        bool kept0 = (kb[i0] != 0);
        bool kept1 = (kb[i1] != 0);
        unsigned long long m =
            *(const unsigned long long*)(kb + c);   // 8 col-keep bytes

        if (!kept0) {
#pragma unroll
            for (int q = 0; q < 8; q++)
                if (!((m >> (8 * q)) & 0xFFull)) v0[q] = 0u;
        }
        if (!kept1) {
#pragma unroll
            for (int q = 0; q < 8; q++)
                if (!((m >> (8 * q)) & 0xFFull)) v1[q] = 0u;
        }
        STG256(out + e0 + c, v0);
        STG256(out + e1 + c, v1);
    } else {
        // generic float4 fallback
        cudaGridDependencySynchronize();
        const unsigned char* kb = g_keep + b * N;
        const uchar4* km = (const uchar4*)kb;
        bool kept0 = (kb[i0] != 0);
        bool kept1 = (kb[i1] != 0);
        int nvec = N >> 2;
        const float4* a0 = (const float4*)(adj + e0);
        const float4* a1 = (const float4*)(adj + e1);
        float4* o0 = (float4*)(out + e0);
        float4* o1 = (float4*)(out + e1);
        for (int j = tid; j < nvec; j += blockDim.x) {
            uchar4 mm = km[j];
            float4 x0 = a0[j], x1 = a1[j];
            if (!kept0) {
                x0.x = mm.x ? x0.x : 0.0f;  x0.y = mm.y ? x0.y : 0.0f;
                x0.z = mm.z ? x0.z : 0.0f;  x0.w = mm.w ? x0.w : 0.0f;
            }
            if (!kept1) {
                x1.x = mm.x ? x1.x : 0.0f;  x1.y = mm.y ? x1.y : 0.0f;
                x1.z = mm.z ? x1.z : 0.0f;  x1.w = mm.w ? x1.w : 0.0f;
            }
            o0[j] = x0;
            o1[j] = x1;
        }
    }
}

extern "C" void kernel_launch(void* const* d_in, const int* in_sizes, int n_in,
                              void* d_out, int out_size) {
    const float* adj   = (const float*)d_in[0];   // [B, N, N] fp32
    const float* score = (const float*)d_in[1];   // [B, N, 1] fp32

    long long n_adj   = in_sizes[0];
    long long n_score = in_sizes[1];
    int N = (int)(n_adj / n_score);               // 2048
    int B = (int)(n_score / N);                   // 16
    int k = N / 2;                                // RATE = 0.5

    topk_radix_kernel<<<B, 256>>>(score, N, k);

    // PDL secondary: one block per row PAIR.
    cudaLaunchConfig_t cfg = {};
    cfg.gridDim  = dim3((unsigned)(B * N / 2));
    cfg.blockDim = dim3(256);
    cfg.stream   = 0;
    cudaLaunchAttribute attr[1];
    attr[0].id = cudaLaunchAttributeProgrammaticStreamSerialization;
    attr[0].val.programmaticStreamSerializationAllowed = 1;
    cfg.attrs    = attr;
    cfg.numAttrs = 1;
    cudaLaunchKernelEx(&cfg, apply_mask_kernel,
                       adj, (float*)d_out, N);
}